// round 1
// baseline (speedup 1.0000x reference)
#include <cuda_runtime.h>
#include <math.h>

// Problem constants
constexpr int B  = 2;
constexpr int S  = 2048;
constexpr int D  = 1024;
constexpr int H  = 16;
constexpr int HD = 64;
constexpr int M  = B * S;          // 4096 rows
static_assert(H * HD == D, "");

// Scratch (static device globals — allocation-free)
__device__ float g_Q[(size_t)M * D];
__device__ float g_K[(size_t)M * D];
__device__ float g_V[(size_t)M * D];
__device__ float g_A[(size_t)M * D];

// ---------------------------------------------------------------------------
// SGEMM: C[M,N] = A[M,K] @ W[K,N] + bias[N]
// 128x128 tile, BK=16, 256 threads, 8x8 per-thread microtile.
// ---------------------------------------------------------------------------
__global__ __launch_bounds__(256) void sgemm_bias_kernel(
    const float* __restrict__ A, const float* __restrict__ W,
    const float* __restrict__ bias, float* __restrict__ C,
    int Mm, int Nn, int Kk)
{
    constexpr int BM = 128, BN = 128, BK = 16;
    __shared__ float As[BK][BM];   // A transposed: As[k][m]
    __shared__ float Ws[BK][BN];   // W natural:    Ws[k][n]

    const int t  = threadIdx.x;
    const int tx = t & 15;
    const int ty = t >> 4;
    const int m0 = blockIdx.y * BM;
    const int n0 = blockIdx.x * BN;

    float acc[8][8];
    #pragma unroll
    for (int i = 0; i < 8; i++)
        #pragma unroll
        for (int j = 0; j < 8; j++) acc[i][j] = 0.f;

    for (int k0 = 0; k0 < Kk; k0 += BK) {
        // Load A tile (128x16) -> As[k][m]
        #pragma unroll
        for (int r = 0; r < 2; r++) {
            int f   = t + r * 256;          // 0..511
            int ar  = f >> 2;               // 0..127
            int ac4 = (f & 3) * 4;          // 0,4,8,12
            float4 v = *(const float4*)(A + (size_t)(m0 + ar) * Kk + k0 + ac4);
            As[ac4 + 0][ar] = v.x;
            As[ac4 + 1][ar] = v.y;
            As[ac4 + 2][ar] = v.z;
            As[ac4 + 3][ar] = v.w;
        }
        // Load W tile (16x128) -> Ws[k][n]
        #pragma unroll
        for (int r = 0; r < 2; r++) {
            int f   = t + r * 256;
            int wr  = f >> 5;               // 0..15
            int wc4 = (f & 31) * 4;         // 0..124
            *(float4*)(&Ws[wr][wc4]) =
                *(const float4*)(W + (size_t)(k0 + wr) * Nn + n0 + wc4);
        }
        __syncthreads();

        #pragma unroll
        for (int k = 0; k < BK; k++) {
            float ra[8], rw[8];
            *(float4*)(ra)     = *(const float4*)(&As[k][ty * 8]);
            *(float4*)(ra + 4) = *(const float4*)(&As[k][ty * 8 + 4]);
            *(float4*)(rw)     = *(const float4*)(&Ws[k][tx * 8]);
            *(float4*)(rw + 4) = *(const float4*)(&Ws[k][tx * 8 + 4]);
            #pragma unroll
            for (int i = 0; i < 8; i++)
                #pragma unroll
                for (int j = 0; j < 8; j++)
                    acc[i][j] += ra[i] * rw[j];
        }
        __syncthreads();
    }

    // Epilogue: add bias, store
    #pragma unroll
    for (int i = 0; i < 8; i++) {
        int row = m0 + ty * 8 + i;
        #pragma unroll
        for (int j = 0; j < 8; j += 4) {
            int col = n0 + tx * 8 + j;
            float4 bb = *(const float4*)(bias + col);
            float4 o;
            o.x = acc[i][j + 0] + bb.x;
            o.y = acc[i][j + 1] + bb.y;
            o.z = acc[i][j + 2] + bb.z;
            o.w = acc[i][j + 3] + bb.w;
            *(float4*)(C + (size_t)row * Nn + col) = o;
        }
    }
}

// ---------------------------------------------------------------------------
// Flash attention (fp32, non-causal), per (b,h): 64 q-rows per CTA,
// iterate key blocks of 64. 256 threads, 4x4 per-thread microtiles.
// Layouts: Q/K/V are [B,S,H,HD] (row stride H*HD=1024 for fixed b,h).
// Output written to [B,S,H*HD].
// ---------------------------------------------------------------------------
constexpr int ATTN_SMEM_FLOATS = 64 * 64 /*Qs*/ + 64 * 68 /*Kts*/ +
                                 64 * 64 /*Vs*/ + 64 * 68 /*Ps*/;
constexpr int ATTN_SMEM_BYTES  = ATTN_SMEM_FLOATS * 4;   // 67584

__global__ __launch_bounds__(256) void attn_kernel(
    const float* __restrict__ Q, const float* __restrict__ K,
    const float* __restrict__ V, float* __restrict__ Out)
{
    extern __shared__ float sm[];
    float* Qs  = sm;                    // [64][64]   Qs[r][d]
    float* Kts = Qs + 64 * 64;          // [64][68]   Kts[d][c]   (K transposed)
    float* Vs  = Kts + 64 * 68;         // [64][64]   Vs[c][d]
    float* Ps  = Vs + 64 * 64;          // [64][68]   Ps[r][c]

    const int t  = threadIdx.x;
    const int tx = t & 15;
    const int ty = t >> 4;
    const int bh = blockIdx.y;
    const int b  = bh / H;
    const int h  = bh % H;
    const int q0 = blockIdx.x * 64;

    const float scale = 0.125f;         // 1/sqrt(64)
    const size_t rowStride = (size_t)H * HD;   // 1024

    const float* Qbase = Q + ((size_t)b * S * H + h) * HD;
    const float* Kbase = K + ((size_t)b * S * H + h) * HD;
    const float* Vbase = V + ((size_t)b * S * H + h) * HD;

    // Load Q tile [64][64]
    #pragma unroll
    for (int r = 0; r < 4; r++) {
        int f  = t + r * 256;           // 0..1023
        int rr = f >> 4;                // 0..63
        int c4 = (f & 15) * 4;          // 0..60
        *(float4*)(Qs + rr * 64 + c4) =
            *(const float4*)(Qbase + (size_t)(q0 + rr) * rowStride + c4);
    }

    float mi[4], li[4], Oa[4][4];
    #pragma unroll
    for (int i = 0; i < 4; i++) {
        mi[i] = -1e30f;
        li[i] = 0.f;
        #pragma unroll
        for (int j = 0; j < 4; j++) Oa[i][j] = 0.f;
    }

    for (int kb = 0; kb < S; kb += 64) {
        __syncthreads();   // previous iter's P@V reads done before overwriting

        // Load K block transposed and V block natural
        #pragma unroll
        for (int r = 0; r < 4; r++) {
            int f  = t + r * 256;
            int rr = f >> 4;            // key row within block
            int c4 = (f & 15) * 4;      // d offset
            float4 kv = *(const float4*)(Kbase + (size_t)(kb + rr) * rowStride + c4);
            Kts[(c4 + 0) * 68 + rr] = kv.x;
            Kts[(c4 + 1) * 68 + rr] = kv.y;
            Kts[(c4 + 2) * 68 + rr] = kv.z;
            Kts[(c4 + 3) * 68 + rr] = kv.w;
            *(float4*)(Vs + rr * 64 + c4) =
                *(const float4*)(Vbase + (size_t)(kb + rr) * rowStride + c4);
        }
        __syncthreads();

        // S = Q @ K^T  (4x4 per thread)
        float acc[4][4];
        #pragma unroll
        for (int i = 0; i < 4; i++)
            #pragma unroll
            for (int j = 0; j < 4; j++) acc[i][j] = 0.f;

        #pragma unroll
        for (int d = 0; d < 64; d++) {
            float qv[4];
            #pragma unroll
            for (int i = 0; i < 4; i++) qv[i] = Qs[(ty * 4 + i) * 64 + d];
            float4 kv = *(const float4*)(Kts + d * 68 + tx * 4);
            #pragma unroll
            for (int i = 0; i < 4; i++) {
                acc[i][0] += qv[i] * kv.x;
                acc[i][1] += qv[i] * kv.y;
                acc[i][2] += qv[i] * kv.z;
                acc[i][3] += qv[i] * kv.w;
            }
        }

        // Online softmax, write P to smem
        #pragma unroll
        for (int i = 0; i < 4; i++) {
            float rmax = -1e30f;
            #pragma unroll
            for (int j = 0; j < 4; j++) rmax = fmaxf(rmax, acc[i][j] * scale);
            #pragma unroll
            for (int msk = 1; msk < 16; msk <<= 1)
                rmax = fmaxf(rmax, __shfl_xor_sync(0xffffffffu, rmax, msk));

            float mnew  = fmaxf(mi[i], rmax);
            float alpha = __expf(mi[i] - mnew);
            float p[4];
            float rsum = 0.f;
            #pragma unroll
            for (int j = 0; j < 4; j++) {
                p[j] = __expf(acc[i][j] * scale - mnew);
                rsum += p[j];
            }
            #pragma unroll
            for (int msk = 1; msk < 16; msk <<= 1)
                rsum += __shfl_xor_sync(0xffffffffu, rsum, msk);

            li[i] = li[i] * alpha + rsum;
            mi[i] = mnew;
            #pragma unroll
            for (int j = 0; j < 4; j++) Oa[i][j] *= alpha;

            *(float4*)(Ps + (ty * 4 + i) * 68 + tx * 4) =
                make_float4(p[0], p[1], p[2], p[3]);
        }
        __syncthreads();

        // O += P @ V
        #pragma unroll
        for (int c = 0; c < 64; c++) {
            float pv[4];
            #pragma unroll
            for (int i = 0; i < 4; i++) pv[i] = Ps[(ty * 4 + i) * 68 + c];
            float4 vv = *(const float4*)(Vs + c * 64 + tx * 4);
            #pragma unroll
            for (int i = 0; i < 4; i++) {
                Oa[i][0] += pv[i] * vv.x;
                Oa[i][1] += pv[i] * vv.y;
                Oa[i][2] += pv[i] * vv.z;
                Oa[i][3] += pv[i] * vv.w;
            }
        }
    }

    // Epilogue: normalize and store to [B,S,H*HD]
    #pragma unroll
    for (int i = 0; i < 4; i++) {
        float inv = 1.0f / li[i];
        int row = b * S + q0 + ty * 4 + i;
        int col = h * HD + tx * 4;
        float4 o;
        o.x = Oa[i][0] * inv;
        o.y = Oa[i][1] * inv;
        o.z = Oa[i][2] * inv;
        o.w = Oa[i][3] * inv;
        *(float4*)(Out + (size_t)row * D + col) = o;
    }
}

// ---------------------------------------------------------------------------
// Launch
// ---------------------------------------------------------------------------
extern "C" void kernel_launch(void* const* d_in, const int* in_sizes, int n_in,
                              void* d_out, int out_size)
{
    const float* x  = (const float*)d_in[0];
    const float* Wq = (const float*)d_in[1];
    const float* bq = (const float*)d_in[2];
    const float* Wk = (const float*)d_in[3];
    const float* bk = (const float*)d_in[4];
    const float* Wv = (const float*)d_in[5];
    const float* bv = (const float*)d_in[6];
    const float* Wo = (const float*)d_in[7];
    const float* bo = (const float*)d_in[8];
    float* out = (float*)d_out;

    float *Qp, *Kp, *Vp, *Ap;
    cudaGetSymbolAddress((void**)&Qp, g_Q);
    cudaGetSymbolAddress((void**)&Kp, g_K);
    cudaGetSymbolAddress((void**)&Vp, g_V);
    cudaGetSymbolAddress((void**)&Ap, g_A);

    cudaFuncSetAttribute(attn_kernel,
                         cudaFuncAttributeMaxDynamicSharedMemorySize,
                         ATTN_SMEM_BYTES);

    dim3 ggrid(D / 128, M / 128);   // (8, 32)

    sgemm_bias_kernel<<<ggrid, 256>>>(x, Wq, bq, Qp, M, D, D);
    sgemm_bias_kernel<<<ggrid, 256>>>(x, Wk, bk, Kp, M, D, D);
    sgemm_bias_kernel<<<ggrid, 256>>>(x, Wv, bv, Vp, M, D, D);

    attn_kernel<<<dim3(S / 64, B * H), 256, ATTN_SMEM_BYTES>>>(Qp, Kp, Vp, Ap);

    sgemm_bias_kernel<<<ggrid, 256>>>(Ap, Wo, bo, out, M, D, D);
}

// round 3
// speedup vs baseline: 1.0867x; 1.0867x over previous
#include <cuda_runtime.h>
#include <cuda_bf16.h>
#include <math.h>

// Problem constants
constexpr int B  = 2;
constexpr int S  = 2048;
constexpr int D  = 1024;
constexpr int H  = 16;
constexpr int HD = 64;
constexpr int M  = B * S;          // 4096 rows
static_assert(H * HD == D, "");

// Scratch (static device globals — allocation-free)
__device__ float g_Q[(size_t)M * D];
__device__ float g_K[(size_t)M * D];
__device__ float g_V[(size_t)M * D];
__device__ float g_A[(size_t)M * D];

// ---------------------------------------------------------------------------
// Helpers
// ---------------------------------------------------------------------------
__device__ __forceinline__ void split_bf16(float x, __nv_bfloat16& h, __nv_bfloat16& l) {
    h = __float2bfloat16(x);
    l = __float2bfloat16(x - __bfloat162float(h));
}

// D += A(16x16) * B(16x8), bf16 in, fp32 acc.  A row-major, B col-major(k x n).
__device__ __forceinline__ void mma16816(float* c, const unsigned* a, const unsigned* b) {
    asm volatile(
        "mma.sync.aligned.m16n8k16.row.col.f32.bf16.bf16.f32 "
        "{%0,%1,%2,%3},{%4,%5,%6,%7},{%8,%9},{%0,%1,%2,%3};\n"
        : "+f"(c[0]), "+f"(c[1]), "+f"(c[2]), "+f"(c[3])
        : "r"(a[0]), "r"(a[1]), "r"(a[2]), "r"(a[3]), "r"(b[0]), "r"(b[1]));
}

// Load A-fragment (m16k16) from bf16 smem plane, row-major with stride SK elems.
// a0:(r,k) a1:(r+8,k) a2:(r,k+8) a3:(r+8,k+8)
template <int SK>
__device__ __forceinline__ void ldfrag_a(unsigned* a, const __nv_bfloat16* base,
                                         int row0, int k0, int lane) {
    int r  = row0 + (lane >> 2);
    int kp = k0 + (lane & 3) * 2;
    a[0] = *(const unsigned*)(base + r * SK + kp);
    a[1] = *(const unsigned*)(base + (r + 8) * SK + kp);
    a[2] = *(const unsigned*)(base + r * SK + kp + 8);
    a[3] = *(const unsigned*)(base + (r + 8) * SK + kp + 8);
}

// Load B-fragment (k16n8) from bf16 smem plane stored as [n][k], stride SK.
template <int SK>
__device__ __forceinline__ void ldfrag_b(unsigned* b, const __nv_bfloat16* base,
                                         int n0, int k0, int lane) {
    int n  = n0 + (lane >> 2);
    int kp = k0 + (lane & 3) * 2;
    b[0] = *(const unsigned*)(base + n * SK + kp);
    b[1] = *(const unsigned*)(base + n * SK + kp + 8);
}

// ---------------------------------------------------------------------------
// Split-bf16 tensor-core GEMM: C[M,N] = A[M,K] @ W[K,N] + bias
// 128x128 CTA tile, BK=32, 256 threads (8 warps, 4x2), warp tile 32x64.
// ---------------------------------------------------------------------------
constexpr int GSK = 34;   // smem k-stride (BK=32 + 2 pad)

__global__ __launch_bounds__(256) void gemm_bias_tc(
    const float* __restrict__ A, const float* __restrict__ W,
    const float* __restrict__ bias, float* __restrict__ C,
    int Kk, int Nn)
{
    constexpr int BM = 128, BN = 128, BK = 32;
    __shared__ __nv_bfloat16 Ah[BM * GSK], Al[BM * GSK];
    __shared__ __nv_bfloat16 Bh[BN * GSK], Bl[BN * GSK];   // [n][k]

    const int t    = threadIdx.x;
    const int lane = t & 31;
    const int wid  = t >> 5;
    const int wm   = wid >> 1;       // 0..3
    const int wn   = wid & 1;        // 0..1
    const int m0   = blockIdx.y * BM;
    const int n0   = blockIdx.x * BN;

    float acc[2][8][4];
    #pragma unroll
    for (int i = 0; i < 2; i++)
        #pragma unroll
        for (int j = 0; j < 8; j++)
            #pragma unroll
            for (int c = 0; c < 4; c++) acc[i][j][c] = 0.f;

    for (int k0 = 0; k0 < Kk; k0 += BK) {
        // A tile: 128x32 floats -> Ah/Al[row][k]
        #pragma unroll
        for (int i = 0; i < 4; i++) {
            int s   = t + i * 256;        // 0..1023 float4 slots
            int row = s >> 3;             // 0..127
            int kc  = (s & 7) * 4;        // 0..28
            float4 v = *(const float4*)(A + (size_t)(m0 + row) * Kk + k0 + kc);
            __nv_bfloat16 h, l;
            split_bf16(v.x, h, l); Ah[row * GSK + kc + 0] = h; Al[row * GSK + kc + 0] = l;
            split_bf16(v.y, h, l); Ah[row * GSK + kc + 1] = h; Al[row * GSK + kc + 1] = l;
            split_bf16(v.z, h, l); Ah[row * GSK + kc + 2] = h; Al[row * GSK + kc + 2] = l;
            split_bf16(v.w, h, l); Ah[row * GSK + kc + 3] = h; Al[row * GSK + kc + 3] = l;
        }
        // W tile: 32x128 floats -> Bh/Bl[n][k] (transposed)
        #pragma unroll
        for (int i = 0; i < 4; i++) {
            int s    = t + i * 256;
            int krow = s >> 5;            // 0..31
            int nc   = (s & 31) * 4;      // 0..124
            float4 v = *(const float4*)(W + (size_t)(k0 + krow) * Nn + n0 + nc);
            __nv_bfloat16 h, l;
            split_bf16(v.x, h, l); Bh[(nc + 0) * GSK + krow] = h; Bl[(nc + 0) * GSK + krow] = l;
            split_bf16(v.y, h, l); Bh[(nc + 1) * GSK + krow] = h; Bl[(nc + 1) * GSK + krow] = l;
            split_bf16(v.z, h, l); Bh[(nc + 2) * GSK + krow] = h; Bl[(nc + 2) * GSK + krow] = l;
            split_bf16(v.w, h, l); Bh[(nc + 3) * GSK + krow] = h; Bl[(nc + 3) * GSK + krow] = l;
        }
        __syncthreads();

        #pragma unroll
        for (int ks = 0; ks < BK; ks += 16) {
            unsigned bh[8][2], bl[8][2];
            #pragma unroll
            for (int ns = 0; ns < 8; ns++) {
                ldfrag_b<GSK>(bh[ns], Bh, wn * 64 + ns * 8, ks, lane);
                ldfrag_b<GSK>(bl[ns], Bl, wn * 64 + ns * 8, ks, lane);
            }
            #pragma unroll
            for (int ms = 0; ms < 2; ms++) {
                unsigned ah[4], al[4];
                ldfrag_a<GSK>(ah, Ah, wm * 32 + ms * 16, ks, lane);
                ldfrag_a<GSK>(al, Al, wm * 32 + ms * 16, ks, lane);
                #pragma unroll
                for (int ns = 0; ns < 8; ns++) {
                    mma16816(acc[ms][ns], ah, bh[ns]);
                    mma16816(acc[ms][ns], ah, bl[ns]);
                    mma16816(acc[ms][ns], al, bh[ns]);
                }
            }
        }
        __syncthreads();
    }

    // Epilogue
    #pragma unroll
    for (int ms = 0; ms < 2; ms++) {
        int row = m0 + wm * 32 + ms * 16 + (lane >> 2);
        #pragma unroll
        for (int ns = 0; ns < 8; ns++) {
            int col = n0 + wn * 64 + ns * 8 + (lane & 3) * 2;
            float b0 = bias[col], b1 = bias[col + 1];
            float2 o;
            o.x = acc[ms][ns][0] + b0;
            o.y = acc[ms][ns][1] + b1;
            *(float2*)(C + (size_t)row * Nn + col) = o;
            o.x = acc[ms][ns][2] + b0;
            o.y = acc[ms][ns][3] + b1;
            *(float2*)(C + (size_t)(row + 8) * Nn + col) = o;
        }
    }
}

// ---------------------------------------------------------------------------
// Split-bf16 tensor-core flash attention.
// Per (b,h): CTA = 64 q-rows; key blocks of 64. 256 threads = 8 warps (4x2).
// Warp S-tile: 16 q x 32 keys.  Warp O-tile: 16 q x 32 d.
// ---------------------------------------------------------------------------
constexpr int ASK = 66;   // bf16 plane k-stride (64 + 2)
constexpr int SST = 68;   // fp32 score stride

constexpr int ATTN_PLANE   = 64 * ASK;                  // bf16 elems
constexpr int ATTN_SMEM_BYTES =
    8 * ATTN_PLANE * 2          /* Qh Ql Kh Kl Vh Vl Ph Pl */
    + 64 * SST * 4              /* Sf */
    + 3 * 64 * 4;               /* rowm rowl rowa */

__global__ __launch_bounds__(256) void attn_tc_kernel(
    const float* __restrict__ Q, const float* __restrict__ K,
    const float* __restrict__ V, float* __restrict__ Out)
{
    extern __shared__ char smraw[];
    __nv_bfloat16* Qh = (__nv_bfloat16*)smraw;
    __nv_bfloat16* Ql = Qh + ATTN_PLANE;
    __nv_bfloat16* Kh = Ql + ATTN_PLANE;   // [key][d]
    __nv_bfloat16* Kl = Kh + ATTN_PLANE;
    __nv_bfloat16* Vh = Kl + ATTN_PLANE;   // [d][key]  (transposed)
    __nv_bfloat16* Vl = Vh + ATTN_PLANE;
    __nv_bfloat16* Ph = Vl + ATTN_PLANE;   // [q][key]
    __nv_bfloat16* Pl = Ph + ATTN_PLANE;
    float* Sf   = (float*)(Pl + ATTN_PLANE);    // [64][SST]
    float* rowm = Sf + 64 * SST;
    float* rowl = rowm + 64;
    float* rowa = rowl + 64;

    const int t    = threadIdx.x;
    const int lane = t & 31;
    const int wid  = t >> 5;
    const int wm   = wid >> 1;     // 0..3
    const int wn   = wid & 1;      // 0..1
    const int bh   = blockIdx.y;
    const int b    = bh / H;
    const int h    = bh % H;
    const int q0   = blockIdx.x * 64;

    const size_t rowStride = (size_t)D;            // 1024
    const float* Qbase = Q + ((size_t)b * S) * D + h * HD;
    const float* Kbase = K + ((size_t)b * S) * D + h * HD;
    const float* Vbase = V + ((size_t)b * S) * D + h * HD;

    // Init softmax state
    if (t < 64) { rowm[t] = -1e30f; rowl[t] = 0.f; }

    // Load + split Q tile [64 q][64 d]
    #pragma unroll
    for (int i = 0; i < 4; i++) {
        int f  = t + i * 256;          // 0..1023
        int rr = f >> 4;               // q row 0..63
        int c4 = (f & 15) * 4;         // d 0..60
        float4 v = *(const float4*)(Qbase + (size_t)(q0 + rr) * rowStride + c4);
        __nv_bfloat16 hh, ll;
        split_bf16(v.x, hh, ll); Qh[rr * ASK + c4 + 0] = hh; Ql[rr * ASK + c4 + 0] = ll;
        split_bf16(v.y, hh, ll); Qh[rr * ASK + c4 + 1] = hh; Ql[rr * ASK + c4 + 1] = ll;
        split_bf16(v.z, hh, ll); Qh[rr * ASK + c4 + 2] = hh; Ql[rr * ASK + c4 + 2] = ll;
        split_bf16(v.w, hh, ll); Qh[rr * ASK + c4 + 3] = hh; Ql[rr * ASK + c4 + 3] = ll;
    }

    float acc_o[4][4];
    #pragma unroll
    for (int i = 0; i < 4; i++)
        #pragma unroll
        for (int j = 0; j < 4; j++) acc_o[i][j] = 0.f;

    for (int kb = 0; kb < S; kb += 64) {
        __syncthreads();   // prior iteration done reading K/V/P planes

        // Load + split K block [key][d] and V block transposed [d][key]
        #pragma unroll
        for (int i = 0; i < 4; i++) {
            int f  = t + i * 256;
            int rr = f >> 4;            // key row 0..63
            int c4 = (f & 15) * 4;      // d
            float4 kv = *(const float4*)(Kbase + (size_t)(kb + rr) * rowStride + c4);
            __nv_bfloat16 hh, ll;
            split_bf16(kv.x, hh, ll); Kh[rr * ASK + c4 + 0] = hh; Kl[rr * ASK + c4 + 0] = ll;
            split_bf16(kv.y, hh, ll); Kh[rr * ASK + c4 + 1] = hh; Kl[rr * ASK + c4 + 1] = ll;
            split_bf16(kv.z, hh, ll); Kh[rr * ASK + c4 + 2] = hh; Kl[rr * ASK + c4 + 2] = ll;
            split_bf16(kv.w, hh, ll); Kh[rr * ASK + c4 + 3] = hh; Kl[rr * ASK + c4 + 3] = ll;

            float4 vv = *(const float4*)(Vbase + (size_t)(kb + rr) * rowStride + c4);
            split_bf16(vv.x, hh, ll); Vh[(c4 + 0) * ASK + rr] = hh; Vl[(c4 + 0) * ASK + rr] = ll;
            split_bf16(vv.y, hh, ll); Vh[(c4 + 1) * ASK + rr] = hh; Vl[(c4 + 1) * ASK + rr] = ll;
            split_bf16(vv.z, hh, ll); Vh[(c4 + 2) * ASK + rr] = hh; Vl[(c4 + 2) * ASK + rr] = ll;
            split_bf16(vv.w, hh, ll); Vh[(c4 + 3) * ASK + rr] = hh; Vl[(c4 + 3) * ASK + rr] = ll;
        }
        __syncthreads();

        // ---- S = Q @ K^T : warp tile 16 q x 32 keys ----
        float acc_s[4][4];
        #pragma unroll
        for (int i = 0; i < 4; i++)
            #pragma unroll
            for (int j = 0; j < 4; j++) acc_s[i][j] = 0.f;

        #pragma unroll
        for (int ks = 0; ks < 64; ks += 16) {
            unsigned ah[4], al[4];
            ldfrag_a<ASK>(ah, Qh, wm * 16, ks, lane);
            ldfrag_a<ASK>(al, Ql, wm * 16, ks, lane);
            #pragma unroll
            for (int ns = 0; ns < 4; ns++) {
                unsigned bhf[2], blf[2];
                ldfrag_b<ASK>(bhf, Kh, wn * 32 + ns * 8, ks, lane);
                ldfrag_b<ASK>(blf, Kl, wn * 32 + ns * 8, ks, lane);
                mma16816(acc_s[ns], ah, bhf);
                mma16816(acc_s[ns], ah, blf);
                mma16816(acc_s[ns], al, bhf);
            }
        }

        // Write scaled scores to Sf
        {
            int r = wm * 16 + (lane >> 2);
            #pragma unroll
            for (int ns = 0; ns < 4; ns++) {
                int c = wn * 32 + ns * 8 + (lane & 3) * 2;
                Sf[r * SST + c]           = acc_s[ns][0] * 0.125f;
                Sf[r * SST + c + 1]       = acc_s[ns][1] * 0.125f;
                Sf[(r + 8) * SST + c]     = acc_s[ns][2] * 0.125f;
                Sf[(r + 8) * SST + c + 1] = acc_s[ns][3] * 0.125f;
            }
        }
        __syncthreads();

        // ---- online softmax: 4 threads per row, 16 cols each ----
        {
            int row = t >> 2;
            int cb  = (t & 3) * 16;
            float mloc = -1e30f;
            #pragma unroll
            for (int j = 0; j < 16; j++)
                mloc = fmaxf(mloc, Sf[row * SST + cb + j]);
            mloc = fmaxf(mloc, __shfl_xor_sync(0xffffffffu, mloc, 1));
            mloc = fmaxf(mloc, __shfl_xor_sync(0xffffffffu, mloc, 2));

            float mold = rowm[row];
            float mnew = fmaxf(mold, mloc);
            float alpha = __expf(mold - mnew);

            float sum = 0.f;
            #pragma unroll
            for (int j = 0; j < 16; j++) {
                float p = __expf(Sf[row * SST + cb + j] - mnew);
                sum += p;
                __nv_bfloat16 hh, ll;
                split_bf16(p, hh, ll);
                Ph[row * ASK + cb + j] = hh;
                Pl[row * ASK + cb + j] = ll;
            }
            sum += __shfl_xor_sync(0xffffffffu, sum, 1);
            sum += __shfl_xor_sync(0xffffffffu, sum, 2);

            if ((t & 3) == 0) {
                rowm[row] = mnew;
                rowl[row] = rowl[row] * alpha + sum;
                rowa[row] = alpha;
            }
        }
        __syncthreads();

        // Rescale O accumulators by alpha of their rows
        {
            float a0 = rowa[wm * 16 + (lane >> 2)];
            float a8 = rowa[wm * 16 + (lane >> 2) + 8];
            #pragma unroll
            for (int ns = 0; ns < 4; ns++) {
                acc_o[ns][0] *= a0;
                acc_o[ns][1] *= a0;
                acc_o[ns][2] *= a8;
                acc_o[ns][3] *= a8;
            }
        }

        // ---- O += P @ V : warp tile 16 q x 32 d ----
        #pragma unroll
        for (int ks = 0; ks < 64; ks += 16) {
            unsigned ah[4], al[4];
            ldfrag_a<ASK>(ah, Ph, wm * 16, ks, lane);
            ldfrag_a<ASK>(al, Pl, wm * 16, ks, lane);
            #pragma unroll
            for (int ns = 0; ns < 4; ns++) {
                unsigned bhf[2], blf[2];
                ldfrag_b<ASK>(bhf, Vh, wn * 32 + ns * 8, ks, lane);
                ldfrag_b<ASK>(blf, Vl, wn * 32 + ns * 8, ks, lane);
                mma16816(acc_o[ns], ah, bhf);
                mma16816(acc_o[ns], ah, blf);
                mma16816(acc_o[ns], al, bhf);
            }
        }
    }

    // Epilogue: normalize rows, store to [B*S, D]
    {
        float inv0 = 1.0f / rowl[wm * 16 + (lane >> 2)];
        float inv8 = 1.0f / rowl[wm * 16 + (lane >> 2) + 8];
        int row = b * S + q0 + wm * 16 + (lane >> 2);
        #pragma unroll
        for (int ns = 0; ns < 4; ns++) {
            int col = h * HD + wn * 32 + ns * 8 + (lane & 3) * 2;
            float2 o;
            o.x = acc_o[ns][0] * inv0;
            o.y = acc_o[ns][1] * inv0;
            *(float2*)(Out + (size_t)row * D + col) = o;
            o.x = acc_o[ns][2] * inv8;
            o.y = acc_o[ns][3] * inv8;
            *(float2*)(Out + (size_t)(row + 8) * D + col) = o;
        }
    }
}

// ---------------------------------------------------------------------------
// Launch
// ---------------------------------------------------------------------------
extern "C" void kernel_launch(void* const* d_in, const int* in_sizes, int n_in,
                              void* d_out, int out_size)
{
    const float* x  = (const float*)d_in[0];
    const float* Wq = (const float*)d_in[1];
    const float* bq = (const float*)d_in[2];
    const float* Wk = (const float*)d_in[3];
    const float* bk = (const float*)d_in[4];
    const float* Wv = (const float*)d_in[5];
    const float* bv = (const float*)d_in[6];
    const float* Wo = (const float*)d_in[7];
    const float* bo = (const float*)d_in[8];
    float* out = (float*)d_out;

    float *Qp, *Kp, *Vp, *Ap;
    cudaGetSymbolAddress((void**)&Qp, g_Q);
    cudaGetSymbolAddress((void**)&Kp, g_K);
    cudaGetSymbolAddress((void**)&Vp, g_V);
    cudaGetSymbolAddress((void**)&Ap, g_A);

    cudaFuncSetAttribute(attn_tc_kernel,
                         cudaFuncAttributeMaxDynamicSharedMemorySize,
                         ATTN_SMEM_BYTES);

    dim3 ggrid(D / 128, M / 128);   // (8, 32)

    gemm_bias_tc<<<ggrid, 256>>>(x, Wq, bq, Qp, D, D);
    gemm_bias_tc<<<ggrid, 256>>>(x, Wk, bk, Kp, D, D);
    gemm_bias_tc<<<ggrid, 256>>>(x, Wv, bv, Vp, D, D);

    attn_tc_kernel<<<dim3(S / 64, B * H), 256, ATTN_SMEM_BYTES>>>(Qp, Kp, Vp, Ap);

    gemm_bias_tc<<<ggrid, 256>>>(Ap, Wo, bo, out, D, D);
}

// round 7
// speedup vs baseline: 2.5366x; 2.3342x over previous
#include <cuda_runtime.h>
#include <cuda_bf16.h>
#include <stdint.h>
#include <math.h>

// Problem constants
constexpr int B  = 2;
constexpr int S  = 2048;
constexpr int D  = 1024;
constexpr int H  = 16;
constexpr int HD = 64;
constexpr int M  = B * S;          // 4096 rows
static_assert(H * HD == D, "");

typedef __nv_bfloat16 bf16;

// ---------------------------------------------------------------------------
// Persistent split-bf16 planes (static device globals — allocation-free)
// ---------------------------------------------------------------------------
__device__ bf16 g_xh[(size_t)M * D], g_xl[(size_t)M * D];
__device__ bf16 g_Qh[(size_t)M * D], g_Ql[(size_t)M * D];
__device__ bf16 g_Kh[(size_t)M * D], g_Kl[(size_t)M * D];
__device__ bf16 g_Vh[(size_t)M * D], g_Vl[(size_t)M * D];
__device__ bf16 g_Oh[(size_t)M * D], g_Ol[(size_t)M * D];
__device__ bf16 g_WTh[4][(size_t)D * D], g_WTl[4][(size_t)D * D];  // [n][k]

// ---------------------------------------------------------------------------
// Helpers
// ---------------------------------------------------------------------------
__device__ __forceinline__ void split_bf16(float x, bf16& h, bf16& l) {
    h = __float2bfloat16(x);
    l = __float2bfloat16(x - __bfloat162float(h));
}
__device__ __forceinline__ unsigned pack2(bf16 a, bf16 b) {
    __nv_bfloat162 p; p.x = a; p.y = b;
    return *(unsigned*)&p;
}
__device__ __forceinline__ uint32_t smem_u32(const void* p) {
    return (uint32_t)__cvta_generic_to_shared(p);
}
__device__ __forceinline__ void cpasync16(uint32_t dst, const void* src) {
    asm volatile("cp.async.cg.shared.global [%0], [%1], 16;\n" :: "r"(dst), "l"(src));
}
__device__ __forceinline__ void cpcommit() {
    asm volatile("cp.async.commit_group;\n");
}
template <int N>
__device__ __forceinline__ void cpwait() {
    asm volatile("cp.async.wait_group %0;\n" :: "n"(N));
}

// D += A(16x16) * B(16x8), bf16 in, fp32 acc.
__device__ __forceinline__ void mma16816(float* c, const unsigned* a, const unsigned* b) {
    asm volatile(
        "mma.sync.aligned.m16n8k16.row.col.f32.bf16.bf16.f32 "
        "{%0,%1,%2,%3},{%4,%5,%6,%7},{%8,%9},{%0,%1,%2,%3};\n"
        : "+f"(c[0]), "+f"(c[1]), "+f"(c[2]), "+f"(c[3])
        : "r"(a[0]), "r"(a[1]), "r"(a[2]), "r"(a[3]), "r"(b[0]), "r"(b[1]));
}

__device__ __forceinline__ void ldmx4(unsigned* r, uint32_t addr) {
    asm volatile("ldmatrix.sync.aligned.m8n8.x4.shared.b16 {%0,%1,%2,%3}, [%4];\n"
                 : "=r"(r[0]), "=r"(r[1]), "=r"(r[2]), "=r"(r[3]) : "r"(addr));
}
__device__ __forceinline__ void ldmx4t(unsigned* r, uint32_t addr) {
    asm volatile("ldmatrix.sync.aligned.m8n8.x4.trans.shared.b16 {%0,%1,%2,%3}, [%4];\n"
                 : "=r"(r[0]), "=r"(r[1]), "=r"(r[2]), "=r"(r[3]) : "r"(addr));
}

// Per-lane addresses for ldmatrix fragment loads.
// A-frag (m16k16), A stored [row][k] stride SK: regs (r,k),(r+8,k),(r,k+8),(r+8,k+8)
template <int SK>
__device__ __forceinline__ uint32_t addrA(const bf16* base, int row0, int k0, int lane) {
    int g = lane >> 3, lr = lane & 7;
    return smem_u32(base + (row0 + (g & 1) * 8 + lr) * SK + k0 + (g >> 1) * 8);
}
// B-frag pair (two n8-tiles), B stored [n][k] stride SK: regs n0.b0, n0.b1, n8.b0, n8.b1
template <int SK>
__device__ __forceinline__ uint32_t addrB(const bf16* base, int n0, int k0, int lane) {
    int g = lane >> 3, lr = lane & 7;
    return smem_u32(base + (n0 + (g >> 1) * 8 + lr) * SK + k0 + (g & 1) * 8);
}
// B-frag pair via transpose: V stored [key][d] stride SK, fragment needs (k=key, n=d).
template <int SK>
__device__ __forceinline__ uint32_t addrBT(const bf16* base, int kk0, int d0, int lane) {
    int g = lane >> 3, lr = lane & 7;
    return smem_u32(base + (kk0 + (g & 1) * 8 + lr) * SK + d0 + (g >> 1) * 8);
}

// ---------------------------------------------------------------------------
// Prep 1: split x into hi/lo bf16 planes.
// ---------------------------------------------------------------------------
__global__ __launch_bounds__(256) void xprep_kernel(const float* __restrict__ x,
                                                    bf16* __restrict__ xh,
                                                    bf16* __restrict__ xl) {
    size_t i4 = (size_t)blockIdx.x * 256 + threadIdx.x;
    float4 v = *(const float4*)(x + i4 * 4);
    bf16 h0, l0, h1, l1, h2, l2, h3, l3;
    split_bf16(v.x, h0, l0); split_bf16(v.y, h1, l1);
    split_bf16(v.z, h2, l2); split_bf16(v.w, h3, l3);
    *(uint2*)(xh + i4 * 4) = make_uint2(pack2(h0, h1), pack2(h2, h3));
    *(uint2*)(xl + i4 * 4) = make_uint2(pack2(l0, l1), pack2(l2, l3));
}

// ---------------------------------------------------------------------------
// Prep 2: transpose-split W [K][N] -> Th/Tl [N][K].
// ---------------------------------------------------------------------------
__global__ __launch_bounds__(256) void wprep_kernel(const float* __restrict__ W,
                                                    bf16* __restrict__ Th,
                                                    bf16* __restrict__ Tl) {
    __shared__ float tile[32][33];
    int n0 = blockIdx.x * 32, k0 = blockIdx.y * 32;
    int tx = threadIdx.x, ty = threadIdx.y;   // 32 x 8
    #pragma unroll
    for (int j = 0; j < 4; j++)
        tile[ty + j * 8][tx] = W[(size_t)(k0 + ty + j * 8) * D + n0 + tx];
    __syncthreads();
    #pragma unroll
    for (int j = 0; j < 4; j++) {
        int nn = ty + j * 8;
        float v = tile[tx][nn];
        bf16 h, l;
        split_bf16(v, h, l);
        Th[(size_t)(n0 + nn) * D + k0 + tx] = h;
        Tl[(size_t)(n0 + nn) * D + k0 + tx] = l;
    }
}

// ---------------------------------------------------------------------------
// Split-bf16 tensor-core GEMM, pre-split operands, cp.async double-buffered.
// C[M,N] = A[M,K] @ B^T[N,K] + bias.  128x128 tile, BK=32, 8 warps (4x2).
// Epilogue: fp32 (Cf) or split-bf16 planes (Ch/Cl).
// ---------------------------------------------------------------------------
constexpr int GSK   = 40;                       // smem k-stride (32 + 8 pad)
constexpr int GPL   = 128 * GSK;                // plane elems
constexpr int GSTG  = 4 * GPL;                  // stage elems (Ah Al Bh Bl)
constexpr int GEMM_SMEM_BYTES = 2 * GSTG * 2;   // 2 stages * bf16

__global__ __launch_bounds__(256) void gemm_tc(
    const bf16* __restrict__ Ah_g, const bf16* __restrict__ Al_g,
    const bf16* __restrict__ Bh_g, const bf16* __restrict__ Bl_g,
    const float* __restrict__ bias,
    float* __restrict__ Cf, bf16* __restrict__ Ch, bf16* __restrict__ Cl)
{
    extern __shared__ __align__(16) char smraw[];
    bf16* sm = (bf16*)smraw;

    const int t    = threadIdx.x;
    const int lane = t & 31;
    const int wid  = t >> 5;
    const int wm   = wid >> 1;       // 0..3
    const int wn   = wid & 1;        // 0..1
    const int m0   = blockIdx.y * 128;
    const int n0   = blockIdx.x * 128;
    constexpr int NIT = D / 32;      // 32

    float acc[2][8][4];
    #pragma unroll
    for (int i = 0; i < 2; i++)
        #pragma unroll
        for (int j = 0; j < 8; j++)
            #pragma unroll
            for (int c = 0; c < 4; c++) acc[i][j][c] = 0.f;

    auto load_stage = [&](int st, int k0) {
        bf16* sAh = sm + st * GSTG;
        bf16* sAl = sAh + GPL;
        bf16* sBh = sAl + GPL;
        bf16* sBl = sBh + GPL;
        #pragma unroll
        for (int i = 0; i < 2; i++) {
            int f   = t + i * 256;         // 0..511
            int row = f >> 2;              // 0..127
            int ce  = (f & 3) * 8;         // k elem offset (16B chunks)
            size_t ga = (size_t)(m0 + row) * D + k0 + ce;
            size_t gb = (size_t)(n0 + row) * D + k0 + ce;
            cpasync16(smem_u32(sAh + row * GSK + ce), Ah_g + ga);
            cpasync16(smem_u32(sAl + row * GSK + ce), Al_g + ga);
            cpasync16(smem_u32(sBh + row * GSK + ce), Bh_g + gb);
            cpasync16(smem_u32(sBl + row * GSK + ce), Bl_g + gb);
        }
        cpcommit();
    };

    load_stage(0, 0);
    int st = 0;
    for (int it = 0; it < NIT; it++) {
        if (it + 1 < NIT) { load_stage(st ^ 1, (it + 1) * 32); cpwait<1>(); }
        else             { cpwait<0>(); }
        __syncthreads();

        bf16* sAh = sm + st * GSTG;
        bf16* sAl = sAh + GPL;
        bf16* sBh = sAl + GPL;
        bf16* sBl = sBh + GPL;

        #pragma unroll
        for (int ks = 0; ks < 32; ks += 16) {
            unsigned bh[8][2], bl[8][2];
            #pragma unroll
            for (int nt = 0; nt < 4; nt++) {
                ldmx4(&bh[nt * 2][0], addrB<GSK>(sBh, wn * 64 + nt * 16, ks, lane));
                ldmx4(&bl[nt * 2][0], addrB<GSK>(sBl, wn * 64 + nt * 16, ks, lane));
            }
            #pragma unroll
            for (int ms = 0; ms < 2; ms++) {
                unsigned ah[4], al[4];
                ldmx4(ah, addrA<GSK>(sAh, wm * 32 + ms * 16, ks, lane));
                ldmx4(al, addrA<GSK>(sAl, wm * 32 + ms * 16, ks, lane));
                #pragma unroll
                for (int ns = 0; ns < 8; ns++) {
                    mma16816(acc[ms][ns], ah, bh[ns]);
                    mma16816(acc[ms][ns], ah, bl[ns]);
                    mma16816(acc[ms][ns], al, bh[ns]);
                }
            }
        }
        __syncthreads();
        st ^= 1;
    }

    // Epilogue
    #pragma unroll
    for (int ms = 0; ms < 2; ms++) {
        int row = m0 + wm * 32 + ms * 16 + (lane >> 2);
        #pragma unroll
        for (int ns = 0; ns < 8; ns++) {
            int col = n0 + wn * 64 + ns * 8 + (lane & 3) * 2;
            float b0 = bias[col], b1 = bias[col + 1];
            float v00 = acc[ms][ns][0] + b0, v01 = acc[ms][ns][1] + b1;
            float v10 = acc[ms][ns][2] + b0, v11 = acc[ms][ns][3] + b1;
            if (Cf) {
                *(float2*)(Cf + (size_t)row * D + col)       = make_float2(v00, v01);
                *(float2*)(Cf + (size_t)(row + 8) * D + col) = make_float2(v10, v11);
            } else {
                bf16 h0, l0, h1, l1;
                split_bf16(v00, h0, l0); split_bf16(v01, h1, l1);
                *(unsigned*)(Ch + (size_t)row * D + col) = pack2(h0, h1);
                *(unsigned*)(Cl + (size_t)row * D + col) = pack2(l0, l1);
                split_bf16(v10, h0, l0); split_bf16(v11, h1, l1);
                *(unsigned*)(Ch + (size_t)(row + 8) * D + col) = pack2(h0, h1);
                *(unsigned*)(Cl + (size_t)(row + 8) * D + col) = pack2(l0, l1);
            }
        }
    }
}

// ---------------------------------------------------------------------------
// Split-bf16 tensor-core flash attention, pre-split Q/K/V.
// CTA = 64 q-rows x (b,h); key blocks of 64. 8 warps (wm 0..3 x wn 0..1).
// Softmax in registers; V^T via ldmatrix.trans; output = split planes.
// ---------------------------------------------------------------------------
constexpr int ASK  = 72;                 // plane stride (64 + 8)
constexpr int APL  = 64 * ASK;           // plane elems
constexpr int ATTN_SMEM_BYTES = 8 * APL * 2 + 2 * 2 * 64 * 4;  // planes + pmax/psum

__global__ __launch_bounds__(256, 2) void attn_tc_kernel(
    const bf16* __restrict__ Qh_g, const bf16* __restrict__ Ql_g,
    const bf16* __restrict__ Kh_g, const bf16* __restrict__ Kl_g,
    const bf16* __restrict__ Vh_g, const bf16* __restrict__ Vl_g,
    bf16* __restrict__ Oh_g, bf16* __restrict__ Ol_g)
{
    extern __shared__ __align__(16) char smraw[];
    bf16* Qh = (bf16*)smraw;
    bf16* Ql = Qh + APL;
    bf16* Kh = Ql + APL;     // [key][d]
    bf16* Kl = Kh + APL;
    bf16* Vh = Kl + APL;     // [key][d]  (transposed on read via ldmatrix.trans)
    bf16* Vl = Vh + APL;
    bf16* Ph = Vl + APL;     // [q][key]
    bf16* Pl = Ph + APL;
    float* pmax = (float*)(Pl + APL);    // [2][64]
    float* psum = pmax + 2 * 64;         // [2][64]

    const int t    = threadIdx.x;
    const int lane = t & 31;
    const int wid  = t >> 5;
    const int wm   = wid >> 1;     // 0..3
    const int wn   = wid & 1;      // 0..1
    const int bh   = blockIdx.y;
    const int b    = bh / H;
    const int h    = bh % H;
    const int q0   = blockIdx.x * 64;

    const size_t rowBase = ((size_t)b * S + q0) * D + h * HD;
    const size_t kvBase  = ((size_t)b * S) * D + h * HD;

    // Q prologue loads (cp.async)
    #pragma unroll
    for (int i = 0; i < 2; i++) {
        int f   = t + i * 256;       // 0..511
        int rr  = f >> 3;            // 0..63
        int ce  = (f & 7) * 8;       // 0..56
        size_t g = rowBase + (size_t)rr * D + ce;
        cpasync16(smem_u32(Qh + rr * ASK + ce), Qh_g + g);
        cpasync16(smem_u32(Ql + rr * ASK + ce), Ql_g + g);
    }
    cpcommit();

    const int r  = wm * 16 + (lane >> 2);   // this thread's first q-row
    float m0 = -1e30f, m8 = -1e30f, l0 = 0.f, l8 = 0.f;
    float acc_o[4][4];
    #pragma unroll
    for (int i = 0; i < 4; i++)
        #pragma unroll
        for (int j = 0; j < 4; j++) acc_o[i][j] = 0.f;

    for (int kb = 0; kb < S; kb += 64) {
        __syncthreads();   // prior P@V finished: safe to overwrite K/V planes

        // K/V block loads
        #pragma unroll
        for (int i = 0; i < 2; i++) {
            int f   = t + i * 256;
            int rr  = f >> 3;
            int ce  = (f & 7) * 8;
            size_t g = kvBase + (size_t)(kb + rr) * D + ce;
            cpasync16(smem_u32(Kh + rr * ASK + ce), Kh_g + g);
            cpasync16(smem_u32(Kl + rr * ASK + ce), Kl_g + g);
            cpasync16(smem_u32(Vh + rr * ASK + ce), Vh_g + g);
            cpasync16(smem_u32(Vl + rr * ASK + ce), Vl_g + g);
        }
        cpcommit();
        cpwait<0>();
        __syncthreads();

        // ---- S = Q @ K^T : warp tile 16 q x 32 keys ----
        float acc_s[4][4];
        #pragma unroll
        for (int i = 0; i < 4; i++)
            #pragma unroll
            for (int j = 0; j < 4; j++) acc_s[i][j] = 0.f;

        #pragma unroll
        for (int ks = 0; ks < 64; ks += 16) {
            unsigned ah[4], al[4], bhf[4][2], blf[4][2];
            ldmx4(ah, addrA<ASK>(Qh, wm * 16, ks, lane));
            ldmx4(al, addrA<ASK>(Ql, wm * 16, ks, lane));
            #pragma unroll
            for (int nt = 0; nt < 2; nt++) {
                ldmx4(&bhf[nt * 2][0], addrB<ASK>(Kh, wn * 32 + nt * 16, ks, lane));
                ldmx4(&blf[nt * 2][0], addrB<ASK>(Kl, wn * 32 + nt * 16, ks, lane));
            }
            #pragma unroll
            for (int ns = 0; ns < 4; ns++) {
                mma16816(acc_s[ns], ah, bhf[ns]);
                mma16816(acc_s[ns], ah, blf[ns]);
                mma16816(acc_s[ns], al, bhf[ns]);
            }
        }

        // Scale scores
        #pragma unroll
        for (int ns = 0; ns < 4; ns++)
            #pragma unroll
            for (int j = 0; j < 4; j++) acc_s[ns][j] *= 0.125f;

        // Per-warp row max (rows r, r+8): reduce over 8 cols then quad shfl
        float pm0 = -1e30f, pm8 = -1e30f;
        #pragma unroll
        for (int ns = 0; ns < 4; ns++) {
            pm0 = fmaxf(pm0, fmaxf(acc_s[ns][0], acc_s[ns][1]));
            pm8 = fmaxf(pm8, fmaxf(acc_s[ns][2], acc_s[ns][3]));
        }
        pm0 = fmaxf(pm0, __shfl_xor_sync(0xffffffffu, pm0, 1));
        pm0 = fmaxf(pm0, __shfl_xor_sync(0xffffffffu, pm0, 2));
        pm8 = fmaxf(pm8, __shfl_xor_sync(0xffffffffu, pm8, 1));
        pm8 = fmaxf(pm8, __shfl_xor_sync(0xffffffffu, pm8, 2));
        if ((lane & 3) == 0) {
            pmax[wn * 64 + r]     = pm0;
            pmax[wn * 64 + r + 8] = pm8;
        }
        __syncthreads();

        float mnew0 = fmaxf(m0, fmaxf(pmax[r],      pmax[64 + r]));
        float mnew8 = fmaxf(m8, fmaxf(pmax[r + 8],  pmax[64 + r + 8]));
        float alpha0 = __expf(m0 - mnew0);
        float alpha8 = __expf(m8 - mnew8);

        // exp, split-store P, partial sums
        float ps0 = 0.f, ps8 = 0.f;
        #pragma unroll
        for (int ns = 0; ns < 4; ns++) {
            int c = wn * 32 + ns * 8 + (lane & 3) * 2;
            float p00 = __expf(acc_s[ns][0] - mnew0);
            float p01 = __expf(acc_s[ns][1] - mnew0);
            float p10 = __expf(acc_s[ns][2] - mnew8);
            float p11 = __expf(acc_s[ns][3] - mnew8);
            ps0 += p00 + p01;
            ps8 += p10 + p11;
            bf16 h0, lo0, h1, lo1;
            split_bf16(p00, h0, lo0); split_bf16(p01, h1, lo1);
            *(unsigned*)(Ph + r * ASK + c) = pack2(h0, h1);
            *(unsigned*)(Pl + r * ASK + c) = pack2(lo0, lo1);
            split_bf16(p10, h0, lo0); split_bf16(p11, h1, lo1);
            *(unsigned*)(Ph + (r + 8) * ASK + c) = pack2(h0, h1);
            *(unsigned*)(Pl + (r + 8) * ASK + c) = pack2(lo0, lo1);
            // rescale O accumulators
            acc_o[ns][0] *= alpha0; acc_o[ns][1] *= alpha0;
            acc_o[ns][2] *= alpha8; acc_o[ns][3] *= alpha8;
        }
        ps0 += __shfl_xor_sync(0xffffffffu, ps0, 1);
        ps0 += __shfl_xor_sync(0xffffffffu, ps0, 2);
        ps8 += __shfl_xor_sync(0xffffffffu, ps8, 1);
        ps8 += __shfl_xor_sync(0xffffffffu, ps8, 2);
        if ((lane & 3) == 0) {
            psum[wn * 64 + r]     = ps0;
            psum[wn * 64 + r + 8] = ps8;
        }
        __syncthreads();   // P planes + psum visible

        l0 = l0 * alpha0 + psum[r]     + psum[64 + r];
        l8 = l8 * alpha8 + psum[r + 8] + psum[64 + r + 8];
        m0 = mnew0; m8 = mnew8;

        // ---- O += P @ V : warp tile 16 q x 32 d (V^T via ldmatrix.trans) ----
        #pragma unroll
        for (int ks = 0; ks < 64; ks += 16) {
            unsigned ah[4], al[4], bhf[4][2], blf[4][2];
            ldmx4(ah, addrA<ASK>(Ph, wm * 16, ks, lane));
            ldmx4(al, addrA<ASK>(Pl, wm * 16, ks, lane));
            #pragma unroll
            for (int nt = 0; nt < 2; nt++) {
                ldmx4t(&bhf[nt * 2][0], addrBT<ASK>(Vh, ks, wn * 32 + nt * 16, lane));
                ldmx4t(&blf[nt * 2][0], addrBT<ASK>(Vl, ks, wn * 32 + nt * 16, lane));
            }
            #pragma unroll
            for (int ns = 0; ns < 4; ns++) {
                mma16816(acc_o[ns], ah, bhf[ns]);
                mma16816(acc_o[ns], ah, blf[ns]);
                mma16816(acc_o[ns], al, bhf[ns]);
            }
        }
    }

    // Epilogue: normalize, split-store to O planes [M][D]
    {
        float inv0 = 1.0f / l0;
        float inv8 = 1.0f / l8;
        size_t row = (size_t)b * S + q0 + r;
        #pragma unroll
        for (int ns = 0; ns < 4; ns++) {
            int col = h * HD + wn * 32 + ns * 8 + (lane & 3) * 2;
            float v00 = acc_o[ns][0] * inv0, v01 = acc_o[ns][1] * inv0;
            float v10 = acc_o[ns][2] * inv8, v11 = acc_o[ns][3] * inv8;
            bf16 h0, lo0, h1, lo1;
            split_bf16(v00, h0, lo0); split_bf16(v01, h1, lo1);
            *(unsigned*)(Oh_g + row * D + col) = pack2(h0, h1);
            *(unsigned*)(Ol_g + row * D + col) = pack2(lo0, lo1);
            split_bf16(v10, h0, lo0); split_bf16(v11, h1, lo1);
            *(unsigned*)(Oh_g + (row + 8) * D + col) = pack2(h0, h1);
            *(unsigned*)(Ol_g + (row + 8) * D + col) = pack2(lo0, lo1);
        }
    }
}

// ---------------------------------------------------------------------------
// Launch
// ---------------------------------------------------------------------------
extern "C" void kernel_launch(void* const* d_in, const int* in_sizes, int n_in,
                              void* d_out, int out_size)
{
    const float* x  = (const float*)d_in[0];
    const float* Wq = (const float*)d_in[1];
    const float* bq = (const float*)d_in[2];
    const float* Wk = (const float*)d_in[3];
    const float* bk = (const float*)d_in[4];
    const float* Wv = (const float*)d_in[5];
    const float* bv = (const float*)d_in[6];
    const float* Wo = (const float*)d_in[7];
    const float* bo = (const float*)d_in[8];
    float* out = (float*)d_out;

    bf16 *xh, *xl, *Qh, *Ql, *Kh, *Kl, *Vh, *Vl, *Oh, *Ol, *WTh, *WTl;
    cudaGetSymbolAddress((void**)&xh, g_xh);
    cudaGetSymbolAddress((void**)&xl, g_xl);
    cudaGetSymbolAddress((void**)&Qh, g_Qh);
    cudaGetSymbolAddress((void**)&Ql, g_Ql);
    cudaGetSymbolAddress((void**)&Kh, g_Kh);
    cudaGetSymbolAddress((void**)&Kl, g_Kl);
    cudaGetSymbolAddress((void**)&Vh, g_Vh);
    cudaGetSymbolAddress((void**)&Vl, g_Vl);
    cudaGetSymbolAddress((void**)&Oh, g_Oh);
    cudaGetSymbolAddress((void**)&Ol, g_Ol);
    cudaGetSymbolAddress((void**)&WTh, g_WTh);
    cudaGetSymbolAddress((void**)&WTl, g_WTl);
    const size_t WSZ = (size_t)D * D;

    cudaFuncSetAttribute(gemm_tc, cudaFuncAttributeMaxDynamicSharedMemorySize,
                         GEMM_SMEM_BYTES);
    cudaFuncSetAttribute(attn_tc_kernel, cudaFuncAttributeMaxDynamicSharedMemorySize,
                         ATTN_SMEM_BYTES);

    // Prep: split x, transpose-split weights
    xprep_kernel<<<(M * D) / 1024, 256>>>(x, xh, xl);
    dim3 wgrid(D / 32, D / 32), wblk(32, 8);
    wprep_kernel<<<wgrid, wblk>>>(Wq, WTh + 0 * WSZ, WTl + 0 * WSZ);
    wprep_kernel<<<wgrid, wblk>>>(Wk, WTh + 1 * WSZ, WTl + 1 * WSZ);
    wprep_kernel<<<wgrid, wblk>>>(Wv, WTh + 2 * WSZ, WTl + 2 * WSZ);
    wprep_kernel<<<wgrid, wblk>>>(Wo, WTh + 3 * WSZ, WTl + 3 * WSZ);

    dim3 ggrid(D / 128, M / 128);   // (8, 32)

    // Projections -> split-bf16 Q/K/V planes
    gemm_tc<<<ggrid, 256, GEMM_SMEM_BYTES>>>(xh, xl, WTh + 0 * WSZ, WTl + 0 * WSZ,
                                             bq, nullptr, Qh, Ql);
    gemm_tc<<<ggrid, 256, GEMM_SMEM_BYTES>>>(xh, xl, WTh + 1 * WSZ, WTl + 1 * WSZ,
                                             bk, nullptr, Kh, Kl);
    gemm_tc<<<ggrid, 256, GEMM_SMEM_BYTES>>>(xh, xl, WTh + 2 * WSZ, WTl + 2 * WSZ,
                                             bv, nullptr, Vh, Vl);

    // Attention -> split-bf16 O planes
    attn_tc_kernel<<<dim3(S / 64, B * H), 256, ATTN_SMEM_BYTES>>>(
        Qh, Ql, Kh, Kl, Vh, Vl, Oh, Ol);

    // Output projection -> fp32 out
    gemm_tc<<<ggrid, 256, GEMM_SMEM_BYTES>>>(Oh, Ol, WTh + 3 * WSZ, WTl + 3 * WSZ,
                                             bo, out, nullptr, nullptr);
}